// round 1
// baseline (speedup 1.0000x reference)
#include <cuda_runtime.h>

#define BB 2
#define NN 2048
#define DIN 1024
#define DOUT 1024
#define HH 16
#define HD 64

// Scratch (static device allocations — allowed)
__device__ float g_q[BB*HH*NN*HD];
__device__ float g_k[BB*HH*NN*HD];
__device__ float g_v[BB*HH*NN*HD];
__device__ float g_ctx[BB*NN*DOUT];

// ---------------------------------------------------------------------------
// Fused QKV SGEMM: C = x @ W{q,k,v}, scattered into [b,h,n,d] layout.
// 128x128 block tile, TK=16, 256 threads, 8x8 micro-tile per thread.
// ---------------------------------------------------------------------------
__global__ __launch_bounds__(256) void qkv_gemm(
    const float* __restrict__ x,
    const float* __restrict__ Wq,
    const float* __restrict__ Wk,
    const float* __restrict__ Wv)
{
    const float* W = (blockIdx.z == 0) ? Wq : (blockIdx.z == 1 ? Wk : Wv);
    float* out = (blockIdx.z == 0) ? g_q : (blockIdx.z == 1 ? g_k : g_v);

    __shared__ float As[16][128];
    __shared__ float Bs[16][128];

    const int tid = threadIdx.x;
    const int bm = blockIdx.y * 128;
    const int bn = blockIdx.x * 128;
    const int tr = (tid >> 4) << 3;   // 0..120
    const int tc = (tid & 15) << 3;   // 0..120

    float acc[8][8];
    #pragma unroll
    for (int i = 0; i < 8; i++)
        #pragma unroll
        for (int j = 0; j < 8; j++) acc[i][j] = 0.f;

    for (int k0 = 0; k0 < DIN; k0 += 16) {
        // Load A tile (128 rows x 16 k), store transposed As[k][m]
        #pragma unroll
        for (int s = 0; s < 2; s++) {
            int slot = tid + s * 256;            // 0..511
            int r  = slot >> 2;                  // 0..127
            int c4 = (slot & 3) << 2;            // 0,4,8,12
            float4 v = *(const float4*)&x[(size_t)(bm + r) * DIN + k0 + c4];
            As[c4 + 0][r] = v.x; As[c4 + 1][r] = v.y;
            As[c4 + 2][r] = v.z; As[c4 + 3][r] = v.w;
        }
        // Load B tile (16 k x 128 n)
        #pragma unroll
        for (int s = 0; s < 2; s++) {
            int slot = tid + s * 256;
            int r  = slot >> 5;                  // 0..15
            int c4 = (slot & 31) << 2;           // 0..124
            *(float4*)&Bs[r][c4] = *(const float4*)&W[(size_t)(k0 + r) * DOUT + bn + c4];
        }
        __syncthreads();

        #pragma unroll
        for (int k = 0; k < 16; k++) {
            float a[8], b[8];
            #pragma unroll
            for (int i = 0; i < 8; i++) a[i] = As[k][tr + i];
            #pragma unroll
            for (int j = 0; j < 8; j++) b[j] = Bs[k][tc + j];
            #pragma unroll
            for (int i = 0; i < 8; i++)
                #pragma unroll
                for (int j = 0; j < 8; j++) acc[i][j] += a[i] * b[j];
        }
        __syncthreads();
    }

    // Epilogue: scatter to [b, h, n, d]
    #pragma unroll
    for (int i = 0; i < 8; i++) {
        int row = bm + tr + i;
        int b_ = row >> 11;        // row / 2048
        int n_ = row & 2047;
        #pragma unroll
        for (int j = 0; j < 8; j++) {
            int col = bn + tc + j;
            int h_ = col >> 6;
            int d_ = col & 63;
            out[(((size_t)(b_ * HH + h_) * NN) + n_) * HD + d_] = acc[i][j];
        }
    }
}

// ---------------------------------------------------------------------------
// Final SGEMM: d_out = g_ctx @ Wo + bo
// ---------------------------------------------------------------------------
__global__ __launch_bounds__(256) void out_gemm(
    const float* __restrict__ Wo,
    const float* __restrict__ bo,
    float* __restrict__ out)
{
    __shared__ float As[16][128];
    __shared__ float Bs[16][128];

    const int tid = threadIdx.x;
    const int bm = blockIdx.y * 128;
    const int bn = blockIdx.x * 128;
    const int tr = (tid >> 4) << 3;
    const int tc = (tid & 15) << 3;

    float acc[8][8];
    #pragma unroll
    for (int i = 0; i < 8; i++)
        #pragma unroll
        for (int j = 0; j < 8; j++) acc[i][j] = 0.f;

    for (int k0 = 0; k0 < DOUT; k0 += 16) {
        #pragma unroll
        for (int s = 0; s < 2; s++) {
            int slot = tid + s * 256;
            int r  = slot >> 2;
            int c4 = (slot & 3) << 2;
            float4 v = *(const float4*)&g_ctx[(size_t)(bm + r) * DOUT + k0 + c4];
            As[c4 + 0][r] = v.x; As[c4 + 1][r] = v.y;
            As[c4 + 2][r] = v.z; As[c4 + 3][r] = v.w;
        }
        #pragma unroll
        for (int s = 0; s < 2; s++) {
            int slot = tid + s * 256;
            int r  = slot >> 5;
            int c4 = (slot & 31) << 2;
            *(float4*)&Bs[r][c4] = *(const float4*)&Wo[(size_t)(k0 + r) * DOUT + bn + c4];
        }
        __syncthreads();

        #pragma unroll
        for (int k = 0; k < 16; k++) {
            float a[8], b[8];
            #pragma unroll
            for (int i = 0; i < 8; i++) a[i] = As[k][tr + i];
            #pragma unroll
            for (int j = 0; j < 8; j++) b[j] = Bs[k][tc + j];
            #pragma unroll
            for (int i = 0; i < 8; i++)
                #pragma unroll
                for (int j = 0; j < 8; j++) acc[i][j] += a[i] * b[j];
        }
        __syncthreads();
    }

    #pragma unroll
    for (int i = 0; i < 8; i++) {
        int row = bm + tr + i;
        #pragma unroll
        for (int j = 0; j < 8; j += 4) {
            int col = bn + tc + j;
            float4 bv = *(const float4*)&bo[col];
            float4 t;
            t.x = acc[i][j + 0] + bv.x;
            t.y = acc[i][j + 1] + bv.y;
            t.z = acc[i][j + 2] + bv.z;
            t.w = acc[i][j + 3] + bv.w;
            *(float4*)&out[(size_t)row * DOUT + col] = t;
        }
    }
}

// ---------------------------------------------------------------------------
// Attention: one thread per q-row, online softmax, K/V tiles of 32 in SMEM.
// scores = relu(q.k) * R_hat(r-k), causal, softmax(scores/8), ctx = attn @ v.
// R_hat = (1+exp(v)) / (1+exp(v - w*R)).
// Output written as [b, n, h*64+d] (row-major [4096, 1024]) for out_gemm.
// ---------------------------------------------------------------------------
__global__ __launch_bounds__(128) void attn_kernel(
    const float* __restrict__ wp,
    const float* __restrict__ vp)
{
    const int qb  = blockIdx.x;   // 0..15 (q tile of 128)
    const int h   = blockIdx.y;   // 0..15
    const int b   = blockIdx.z;   // 0..1
    const int tid = threadIdx.x;
    const int r   = qb * 128 + tid;   // this thread's q row

    const size_t head_off = (size_t)(b * HH + h) * NN * HD;
    const float* qbase = g_q + head_off;
    const float* kbase = g_k + head_off;
    const float* vbase = g_v + head_off;

    const float wh = wp[h];
    const float vh = vp[h];
    const float c1 = 1.f + __expf(vh);

    float qreg[64];
    #pragma unroll
    for (int i = 0; i < 16; i++) {
        float4 t = *(const float4*)&qbase[(size_t)r * HD + i * 4];
        qreg[i * 4 + 0] = t.x; qreg[i * 4 + 1] = t.y;
        qreg[i * 4 + 2] = t.z; qreg[i * 4 + 3] = t.w;
    }

    float acc[64];
    #pragma unroll
    for (int d = 0; d < 64; d++) acc[d] = 0.f;

    float m = -1e30f;
    float lsum = 0.f;

    __shared__ float Ks[32][64];
    __shared__ float Vs[32][64];

    const int ktiles = (qb + 1) * 4;   // k up to qb*128+127, tiles of 32

    for (int kt = 0; kt < ktiles; kt++) {
        const int k0 = kt * 32;
        // cooperative load of K/V tile: 32x64 floats each
        #pragma unroll
        for (int s = 0; s < 4; s++) {
            int slot = tid + s * 128;        // 0..511
            int rr  = slot >> 4;             // 0..31
            int c4  = (slot & 15) << 2;      // 0..60
            *(float4*)&Ks[rr][c4] = *(const float4*)&kbase[(size_t)(k0 + rr) * HD + c4];
            *(float4*)&Vs[rr][c4] = *(const float4*)&vbase[(size_t)(k0 + rr) * HD + c4];
        }
        __syncthreads();

        float l[32];
        float tmax = -1e30f;
        #pragma unroll
        for (int j = 0; j < 32; j++) {
            int kidx = k0 + j;
            float s = 0.f;
            #pragma unroll
            for (int d = 0; d < 64; d++) s += qreg[d] * Ks[j][d];
            s = fmaxf(s, 0.f);
            float R = (float)(r - kidx);
            float rhat = c1 / (1.f + __expf(vh - wh * R));
            float logit = s * rhat * 0.125f;
            l[j] = (kidx <= r) ? logit : -1e30f;
            tmax = fmaxf(tmax, l[j]);
        }

        float mnew  = fmaxf(m, tmax);
        float scale = __expf(m - mnew);
        lsum *= scale;
        #pragma unroll
        for (int d = 0; d < 64; d++) acc[d] *= scale;

        #pragma unroll
        for (int j = 0; j < 32; j++) {
            float p = __expf(l[j] - mnew);
            lsum += p;
            #pragma unroll
            for (int d = 0; d < 64; d++) acc[d] += p * Vs[j][d];
        }
        m = mnew;
        __syncthreads();
    }

    const float inv = 1.f / lsum;
    float* outp = g_ctx + ((size_t)(b * NN + r) * DOUT) + h * HD;
    #pragma unroll
    for (int i = 0; i < 16; i++) {
        float4 t;
        t.x = acc[i * 4 + 0] * inv;
        t.y = acc[i * 4 + 1] * inv;
        t.z = acc[i * 4 + 2] * inv;
        t.w = acc[i * 4 + 3] * inv;
        *(float4*)&outp[i * 4] = t;
    }
}

// ---------------------------------------------------------------------------
extern "C" void kernel_launch(void* const* d_in, const int* in_sizes, int n_in,
                              void* d_out, int out_size)
{
    const float* x  = (const float*)d_in[0];
    const float* Wq = (const float*)d_in[1];
    const float* Wk = (const float*)d_in[2];
    const float* Wv = (const float*)d_in[3];
    const float* Wo = (const float*)d_in[4];
    const float* bo = (const float*)d_in[5];
    const float* w  = (const float*)d_in[6];
    const float* v  = (const float*)d_in[7];
    float* out = (float*)d_out;

    // 1. QKV projections: [4096,1024] @ [1024,1024] x3
    dim3 g1(DOUT / 128, (BB * NN) / 128, 3);
    qkv_gemm<<<g1, 256>>>(x, Wq, Wk, Wv);

    // 2. Attention
    dim3 g2(NN / 128, HH, BB);
    attn_kernel<<<g2, 128>>>(w, v);

    // 3. Output projection + bias
    dim3 g3(DOUT / 128, (BB * NN) / 128, 1);
    out_gemm<<<g3, 256>>>(Wo, bo, out);
}